// round 14
// baseline (speedup 1.0000x reference)
#include <cuda_runtime.h>
#include <cuda_bf16.h>
#include <cuda_fp16.h>
#include <math.h>
#include <stdint.h>

// Problem constants
#define BB   2
#define RR   4096
#define SC   48
#define SFN  48
#define CF   32
#define RES  256
#define HID  64
#define ODIM 33
#define NRAY  (BB*RR)    // 8192
#define NSAMP (NRAY*SC)  // 393216

#define DELTA_F ((2.0f - 0.1f) / (float)(SC - 1))

typedef unsigned long long ull;

__device__ __forceinline__ float softplus_fast(float x) {
    float l = __logf(1.f + __expf(-fabsf(x)));
    return (x > 0.f) ? (x + l) : l;
}

__device__ __forceinline__ uint32_t smem_u32(const void* p) {
    uint32_t a;
    asm("{ .reg .u64 t; cvta.to.shared.u64 t, %1; cvt.u32.u64 %0, t; }" : "=r"(a) : "l"(p));
    return a;
}

// ---- mma / ldmatrix wrappers (base PTX) ----
__device__ __forceinline__ void ldsm_x4(uint32_t& r0, uint32_t& r1, uint32_t& r2, uint32_t& r3, uint32_t addr) {
    asm volatile("ldmatrix.sync.aligned.m8n8.x4.shared.b16 {%0,%1,%2,%3}, [%4];"
        : "=r"(r0), "=r"(r1), "=r"(r2), "=r"(r3) : "r"(addr));
}
__device__ __forceinline__ void mma16816h(float& d0, float& d1, float& d2, float& d3,
                                           uint32_t a0, uint32_t a1, uint32_t a2, uint32_t a3,
                                           uint32_t b0, uint32_t b1) {
    asm volatile("mma.sync.aligned.m16n8k16.row.col.f32.f16.f16.f32 "
        "{%0,%1,%2,%3}, {%4,%5,%6,%7}, {%8,%9}, {%0,%1,%2,%3};"
        : "+f"(d0), "+f"(d1), "+f"(d2), "+f"(d3)
        : "r"(a0), "r"(a1), "r"(a2), "r"(a3), "r"(b0), "r"(b1));
}

__device__ __forceinline__ uint32_t packhf(float lo, float hi) {
    __half2 h2; h2.x = __float2half_rn(lo); h2.y = __float2half_rn(hi);
    return *(uint32_t*)&h2;
}
__device__ __forceinline__ uint32_t hfma2u(uint32_t a, uint32_t b, uint32_t c) {
    __half2 r = __hfma2(*(__half2*)&a, *(__half2*)&b, *(__half2*)&c);
    return *(uint32_t*)&r;
}
__device__ __forceinline__ uint32_t hadd2u(uint32_t a, uint32_t b) {
    __half2 r = __hadd2(*(__half2*)&a, *(__half2*)&b);
    return *(uint32_t*)&r;
}

// -------- device scratch --------
__device__ __half g_planes_h[(size_t)BB*3*RES*RES*CF]; // [b,p,y,x,c] fp16, 25MB
__device__ float g_depths_c[NSAMP];
__device__ float g_depths_f[NSAMP];
__device__ float g_sigma_c[NSAMP];
__device__ float g_sigma_f[NSAMP];
__device__ __half g_rgb_c[(size_t)NSAMP*32];           // fp16 rgb, 24MB
__device__ __half g_rgb_f[(size_t)NSAMP*32];
__device__ uint32_t g_Bt1[64*32];    // 8KB
__device__ uint32_t g_Bt2[40*32];    // 5KB

// -------- merged: transpose planes to fp16 + weight prep --------
__global__ void k_trans_prep(const float* __restrict__ in,
                             const float* __restrict__ w1, const float* __restrict__ w2) {
    if (blockIdx.x == RES*RES/32) {
        if (blockIdx.z != 0) return;
        int t = threadIdx.y*32 + threadIdx.x;
        for (int i = t; i < 64*32; i += 1024) g_Bt1[i] = 0;
        for (int i = t; i < 40*32; i += 1024) g_Bt2[i] = 0;
        __syncthreads();
        for (int e = t; e < 64*32; e += 1024) {
            int n = e >> 5, k = e & 31;
            float v = w1[k*HID + n] * (1.f/3.f);
            uint32_t pos = (uint32_t)n*128u + ((((uint32_t)k >> 3) ^ (n & 7)) << 4) + (k & 7)*2u;
            *(__half*)((char*)g_Bt1 + pos) = __float2half_rn(v);
        }
        for (int e = t; e < 33*64; e += 1024) {
            int n = e >> 6, k = e & 63;
            int out = (n < 32) ? (n + 1) : 0;
            float v = w2[k*ODIM + out];
            uint32_t pos = (uint32_t)n*128u + ((((uint32_t)k >> 3) ^ (n & 7)) << 4) + (k & 7)*2u;
            *(__half*)((char*)g_Bt2 + pos) = __float2half_rn(v);
        }
        return;
    }
    __shared__ float tile[32][33];
    int bp = blockIdx.z;
    int m0 = blockIdx.x * 32;
    int tx = threadIdx.x, ty = threadIdx.y;
    tile[ty][tx] = in[((size_t)bp*CF + ty)*(RES*RES) + m0 + tx];
    __syncthreads();
    g_planes_h[((size_t)bp*(RES*RES) + (m0 + ty))*CF + tx] = __float2half_rn(tile[tx][ty]);
}

// -------- fused eval: precomputed-offset fp16 gather + fp16 mma MLP --------
__global__ void __launch_bounds__(128, 6) k_eval_m(
    const float* __restrict__ ro, const float* __restrict__ rd,
    const float* __restrict__ b1, const float* __restrict__ b2,
    const float* __restrict__ nstrat, int fine)
{
    __shared__ __align__(16) char sA[128*128];    // 16KB
    __shared__ __align__(16) char sB1[64*128];    // 8KB
    __shared__ __align__(16) char sB2[40*128];    // 5KB
    __shared__ uint32_t sOff[6][128];             // 3KB
    __shared__ uint32_t sWgt[6][128];             // 3KB
    __shared__ float sb1[HID];
    __shared__ float sb2p[40];

    int tid = threadIdx.x;
    {
        uint4* d1 = (uint4*)sB1; const uint4* s1 = (const uint4*)g_Bt1;
        for (int i = tid; i < 512; i += 128) d1[i] = s1[i];
        uint4* d2 = (uint4*)sB2; const uint4* s2 = (const uint4*)g_Bt2;
        for (int i = tid; i < 320; i += 128) d2[i] = s2[i];
    }
    if (tid < HID) sb1[tid] = b1[tid];
    if (tid < 40)  sb2p[tid] = (tid < 32) ? b2[tid + 1] : ((tid == 32) ? b2[0] : 0.f);

    int idx = blockIdx.x * 128 + tid;
    float*  sigma_out = fine ? g_sigma_f : g_sigma_c;
    __half* rgb_out   = fine ? g_rgb_f   : g_rgb_c;

    // ---- phase 1: per-sample offsets + corner weights ----
    {
        int ray = idx / SC;
        float t;
        if (fine) {
            t = g_depths_f[idx];
        } else {
            int s = idx % SC;
            t = 0.1f + (float)s * DELTA_F + nstrat[idx] * DELTA_F;
            g_depths_c[idx] = t;
        }
        int bb = (idx >= NSAMP/2) ? 1 : 0;
        float cc[3];
        cc[0] = (ro[ray*3+0] + t*rd[ray*3+0]) * 0.5f;
        cc[1] = (ro[ray*3+1] + t*rd[ray*3+1]) * 0.5f;
        cc[2] = (ro[ray*3+2] + t*rd[ray*3+2]) * 0.5f;
#pragma unroll
        for (int p = 0; p < 3; p++) {
            float x = ((cc[p] + 1.f)*(float)RES - 1.f)*0.5f;
            float y = ((cc[(p+1)%3] + 1.f)*(float)RES - 1.f)*0.5f;
            float x0f = floorf(x), y0f = floorf(y);
            float wx1 = x - x0f, wy1 = y - y0f;
            int x0 = (int)x0f, y0 = (int)y0f;
            int xs = min(max(x0, 0), RES-2);
            float wxc0 = (xs == x0) ? (1.f - wx1) : ((xs == x0+1) ? wx1 : 0.f);
            float wxc1 = (xs+1 == x0) ? (1.f - wx1) : ((xs+1 == x0+1) ? wx1 : 0.f);
            uint32_t pb = (uint32_t)(bb*3 + p) * (RES*RES*CF*2u);
#pragma unroll
            for (int cy = 0; cy < 2; cy++) {
                int yy = y0 + cy;
                float wyv = cy ? wy1 : (1.f - wy1);
                if (yy < 0 || yy >= RES) wyv = 0.f;
                int yyc = min(max(yy, 0), RES-1);
                sOff[p*2+cy][tid] = pb + (uint32_t)(yyc*RES + xs) * (CF*2u);
                sWgt[p*2+cy][tid] = packhf(wxc0*wyv, wxc1*wyv);
            }
        }
    }
    __syncwarp();   // warp-local consumers only

    int wid = tid >> 5, l = tid & 31;

    // ---- phase 2: cooperative gather, 2 batches of 3 loads (reg diet) ----
    {
        int bcorner = (l >> 2) & 1;
        int cb = l & 3;
        uint32_t lane_byte = (uint32_t)(l & 7) * 16u;
        const char* pbase = (const char*)g_planes_h;
#pragma unroll 1
        for (int g = 0; g < 8; g++) {
            int s_loc = wid*32 + g*4 + (l >> 3);
            uint32_t acc[4] = {0u, 0u, 0u, 0u};
#pragma unroll
            for (int half6 = 0; half6 < 2; half6++) {
                uint4 v[3];
                uint32_t wu[3];
#pragma unroll
                for (int q = 0; q < 3; q++) {
                    int j = half6*3 + q;
                    uint32_t off = sOff[j][s_loc];
                    uint32_t w2 = sWgt[j][s_loc];
                    uint32_t h = bcorner ? (w2 >> 16) : (w2 & 0xFFFFu);
                    wu[q] = h | (h << 16);
                    v[q] = *(const uint4*)(pbase + off + lane_byte);
                }
#pragma unroll
                for (int q = 0; q < 3; q++) {
                    const uint32_t* hp = (const uint32_t*)&v[q];
#pragma unroll
                    for (int h = 0; h < 4; h++)
                        acc[h] = hfma2u(wu[q], hp[h], acc[h]);
                }
            }
#pragma unroll
            for (int h = 0; h < 4; h++) {
                uint32_t other = __shfl_xor_sync(0xFFFFFFFFu, acc[h], 4);
                acc[h] = hadd2u(acc[h], other);
            }
            if (!(l & 4)) {
                uint32_t rb = (uint32_t)s_loc * 128u;
                uint32_t sw = (uint32_t)(s_loc & 7);
                *(uint4*)(sA + rb + ((((uint32_t)cb) ^ sw) << 4)) = make_uint4(acc[0], acc[1], acc[2], acc[3]);
            }
        }
    }
    __syncthreads();   // B-tiles visibility

    uint32_t aBase  = smem_u32(sA);
    uint32_t b1Base = smem_u32(sB1);
    uint32_t b2Base = smem_u32(sB2);

    int lq = l >> 2;
    int lr2 = (l & 3) * 2;

#pragma unroll
    for (int m = 0; m < 2; m++) {
        int R = wid*32 + m*16;

        uint32_t af[2][4];
        {
            int arow = R + (l & 7) + 8*((l >> 3) & 1);
            uint32_t aseg = (uint32_t)(l >> 4);
            uint32_t rb = (uint32_t)arow * 128u;
            uint32_t sw = (uint32_t)(arow & 7);
#pragma unroll
            for (int kt = 0; kt < 2; kt++) {
                uint32_t addr = aBase + rb + ((((uint32_t)kt*2u + aseg) ^ sw) << 4);
                ldsm_x4(af[kt][0], af[kt][1], af[kt][2], af[kt][3], addr);
            }
        }

        // layer 1: D = a * W (K=32)
        uint32_t a2f[4][4];
        {
            int brow = (l & 7);
            uint32_t bchunk = (uint32_t)(l >> 3);
#pragma unroll
            for (int nt = 0; nt < 8; nt++) {
                int bn = nt*8 + brow;
                uint32_t brb = (uint32_t)bn * 128u;
                uint32_t bsw = (uint32_t)(bn & 7);
                uint32_t hA0, hA1, hB0, hB1;
                ldsm_x4(hA0, hA1, hB0, hB1, b1Base + brb + ((bchunk ^ bsw) << 4));
                float d0 = 0.f, d1 = 0.f, d2 = 0.f, d3 = 0.f;
                mma16816h(d0,d1,d2,d3, af[0][0],af[0][1],af[0][2],af[0][3], hA0,hA1);
                mma16816h(d0,d1,d2,d3, af[1][0],af[1][1],af[1][2],af[1][3], hB0,hB1);

                int col0 = nt*8 + lr2;
                float s0 = softplus_fast(d0 + sb1[col0]);
                float s1 = softplus_fast(d1 + sb1[col0+1]);
                float s2 = softplus_fast(d2 + sb1[col0]);
                float s3 = softplus_fast(d3 + sb1[col0+1]);
                int kk = nt >> 1, half = nt & 1;
                a2f[kk][2*half+0] = packhf(s0, s1);
                a2f[kk][2*half+1] = packhf(s2, s3);
            }
        }

        // layer 2: D = h * W (K=64) ; N=40 permuted
        {
            int brow = (l & 7);
            uint32_t bchunk = (uint32_t)(l >> 3);
            int r0 = blockIdx.x*128 + R + lq;
            int r1 = r0 + 8;
#pragma unroll
            for (int nt2 = 0; nt2 < 5; nt2++) {
                int bn = nt2*8 + brow;
                uint32_t brb = (uint32_t)bn * 128u;
                uint32_t bsw = (uint32_t)(bn & 7);
                uint32_t e0r[4], e1r[4];
                ldsm_x4(e0r[0], e0r[1], e0r[2], e0r[3], b2Base + brb + (((bchunk      ) ^ bsw) << 4));
                ldsm_x4(e1r[0], e1r[1], e1r[2], e1r[3], b2Base + brb + (((4u + bchunk) ^ bsw) << 4));

                float d0 = 0.f, d1 = 0.f, d2 = 0.f, d3 = 0.f;
                mma16816h(d0,d1,d2,d3, a2f[0][0],a2f[0][1],a2f[0][2],a2f[0][3], e0r[0],e0r[1]);
                mma16816h(d0,d1,d2,d3, a2f[1][0],a2f[1][1],a2f[1][2],a2f[1][3], e0r[2],e0r[3]);
                mma16816h(d0,d1,d2,d3, a2f[2][0],a2f[2][1],a2f[2][2],a2f[2][3], e1r[0],e1r[1]);
                mma16816h(d0,d1,d2,d3, a2f[3][0],a2f[3][1],a2f[3][2],a2f[3][3], e1r[2],e1r[3]);

                int col0 = nt2*8 + lr2;
                if (nt2 < 4) {
                    float v0 = __fdividef(1.002f, 1.f + __expf(-(d0 + sb2p[col0])))   - 0.001f;
                    float v1 = __fdividef(1.002f, 1.f + __expf(-(d1 + sb2p[col0+1]))) - 0.001f;
                    float v2 = __fdividef(1.002f, 1.f + __expf(-(d2 + sb2p[col0])))   - 0.001f;
                    float v3 = __fdividef(1.002f, 1.f + __expf(-(d3 + sb2p[col0+1]))) - 0.001f;
                    *(uint32_t*)&rgb_out[(size_t)r0*32 + col0] = packhf(v0, v1);
                    *(uint32_t*)&rgb_out[(size_t)r1*32 + col0] = packhf(v2, v3);
                } else if (lr2 == 0) {
                    sigma_out[r0] = d0 + sb2p[32];
                    sigma_out[r1] = d2 + sb2p[32];
                }
            }
        }
    }
}

// -------- warp-per-ray: coarse march weights + inverse-CDF sampling --------
__global__ void __launch_bounds__(128, 8) k_importance(const float* __restrict__ nimp) {
    int gw   = (blockIdx.x * 128 + threadIdx.x) >> 5;
    int lane = threadIdx.x & 31;
    int wl   = threadIdx.x >> 5;
    __shared__ float sh_d[4][48], sh_s[4][48];
    __shared__ float sh_a[4][48];
    __shared__ float sh_w[4][48];
    __shared__ float sh_cdf[4][46];
    __shared__ float sh_bins[4][48];
    if (gw >= NRAY) return;

    const float* dp = g_depths_c + (size_t)gw*SC;
    const float* sp = g_sigma_c  + (size_t)gw*SC;
    for (int i = lane; i < 48; i += 32) { sh_d[wl][i] = dp[i]; sh_s[wl][i] = sp[i]; }
    __syncwarp();

    for (int i = lane; i < 47; i += 32) {
        float d0 = sh_d[wl][i], d1 = sh_d[wl][i+1];
        float dens = softplus_fast(0.5f*(sh_s[wl][i] + sh_s[wl][i+1]) - 1.f);
        sh_a[wl][i]    = 1.f - __expf(-dens*(d1 - d0));
        sh_bins[wl][i] = 0.5f*(d0 + d1);
    }
    __syncwarp();

    if (lane == 0) {
        float T = 1.f;
        for (int i = 0; i < 47; i++) {
            float a = sh_a[wl][i];
            sh_w[wl][i] = a * T;
            T *= (1.f - a + 1e-10f);
        }
    }
    __syncwarp();

    for (int j = lane; j < 45; j += 32) {
        float m1 = fmaxf(sh_w[wl][j],   sh_w[wl][j+1]);
        float m2 = fmaxf(sh_w[wl][j+1], sh_w[wl][j+2]);
        sh_a[wl][j] = 0.5f*(m1 + m2) + 0.01f + 1e-5f;
    }
    __syncwarp();

    if (lane == 0) {
        float c = 0.f;
        sh_cdf[wl][0] = 0.f;
        for (int j = 0; j < 45; j++) { c += sh_a[wl][j]; sh_cdf[wl][j+1] = c; }
        sh_w[wl][47] = c;
    }
    __syncwarp();
    float inv = __fdividef(1.f, sh_w[wl][47]);
    for (int j = lane + 1; j < 46; j += 32) sh_cdf[wl][j] *= inv;
    __syncwarp();

    const float* up = nimp + (size_t)gw*SFN;
    float* outp = g_depths_f + (size_t)gw*SFN;
    for (int j = lane; j < SFN; j += 32) {
        float u = up[j];
        int ind = 0;
#pragma unroll
        for (int t2 = 0; t2 < 46; t2++) ind += (sh_cdf[wl][t2] <= u) ? 1 : 0;
        int below = ind - 1; if (below < 0) below = 0;
        int above = ind;     if (above > 45) above = 45;
        float cb = sh_cdf[wl][below], ca = sh_cdf[wl][above];
        float bb = sh_bins[wl][below], ba = sh_bins[wl][above];
        float den = ca - cb; if (den < 1e-5f) den = 1.f;
        outp[j] = bb + (u - cb)/den * (ba - bb);
    }
}

// -------- merge, sort, scan-based ray march, outputs --------
__global__ void __launch_bounds__(256) k_final(float* __restrict__ out) {
    int warp = (blockIdx.x * blockDim.x + threadIdx.x) >> 5;
    int lane = threadIdx.x & 31;
    int wl   = threadIdx.x >> 5;
    __shared__ float ds[8][96];
    __shared__ float ss[8][96];
    __shared__ int   ord[8][96];
    __shared__ float scanA[8][96];
    __shared__ float scanB[8][96];
    __shared__ float sal[8][96];
    __shared__ float sdm[8][96];
    __shared__ float swt[8][97];
    if (warp >= NRAY) return;
    int ray = warp;

    for (int k = lane; k < 96; k += 32) {
        float dv, sv;
        if (k < SC) { dv = g_depths_c[(size_t)ray*SC + k]; sv = g_sigma_c[(size_t)ray*SC + k]; }
        else        { dv = g_depths_f[(size_t)ray*SFN + k - SC]; sv = g_sigma_f[(size_t)ray*SFN + k - SC]; }
        ds[wl][k] = dv; ss[wl][k] = sv;
    }
    __syncwarp();

    for (int k = lane; k < 96; k += 32) {
        float di = ds[wl][k];
        int r = 0;
        for (int j = 0; j < 96; j++) {
            float dj = ds[wl][j];
            r += (dj < di) || (dj == di && j < k);
        }
        ord[wl][r] = k;
    }
    __syncwarp();

#pragma unroll
    for (int sblk = 0; sblk < 3; sblk++) {
        int i = lane + sblk*32;
        if (i == 0) {
            scanA[wl][0] = 1.f;
            sal[wl][0] = 0.f;
            sdm[wl][0] = 0.f;
        } else {
            int ip = ord[wl][i-1], ic = ord[wl][i];
            float d0 = ds[wl][ip], d1 = ds[wl][ic];
            float s0 = ss[wl][ip], s1 = ss[wl][ic];
            float dens  = softplus_fast(0.5f*(s0 + s1) - 1.f);
            float alpha = 1.f - __expf(-dens*(d1 - d0));
            scanA[wl][i] = 1.f - alpha + 1e-10f;
            sal[wl][i] = alpha;
            sdm[wl][i] = 0.5f*(d0 + d1);
        }
    }
    __syncwarp();

    {
        float (*src)[96] = scanA; float (*dst)[96] = scanB;
#pragma unroll
        for (int dstep = 1; dstep < 96; dstep <<= 1) {
#pragma unroll
            for (int sblk = 0; sblk < 3; sblk++) {
                int s = lane + sblk*32;
                float v = src[wl][s];
                if (s >= dstep) v *= src[wl][s - dstep];
                dst[wl][s] = v;
            }
            __syncwarp();
            float (*tmp)[96] = src; src = dst; dst = tmp;
        }
#pragma unroll
        for (int sblk = 0; sblk < 3; sblk++) {
            int i = lane + sblk*32;
            swt[wl][i] = (i >= 1) ? sal[wl][i] * src[wl][i-1] : 0.f;
        }
        if (lane == 0) swt[wl][96] = 0.f;
        __syncwarp();

        float wtp = 0.f, daccp = 0.f;
#pragma unroll
        for (int sblk = 0; sblk < 3; sblk++) {
            int i = lane + sblk*32;
            float w = swt[wl][i];
            wtp += w;
            daccp += w * sdm[wl][i];
            sal[wl][ord[wl][i]] = 0.5f*(swt[wl][i] + swt[wl][i+1]);
        }
        __syncwarp();
#pragma unroll
        for (int o = 16; o > 0; o >>= 1) {
            wtp   += __shfl_xor_sync(0xFFFFFFFFu, wtp, o);
            daccp += __shfl_xor_sync(0xFFFFFFFFu, daccp, o);
        }

        float acc = 0.f;
        const __half* pc = g_rgb_c + (size_t)ray*SC*32 + lane;
        const __half* pf = g_rgb_f + (size_t)ray*SFN*32 + lane;
#pragma unroll 8
        for (int k = 0; k < 48; k++) acc += sal[wl][k] * __half2float(pc[(size_t)k*32]);
#pragma unroll 8
        for (int k = 0; k < 48; k++) acc += sal[wl][48+k] * __half2float(pf[(size_t)k*32]);

        out[(size_t)ray*32 + lane] = acc*2.f - 1.f;
        if (lane == 0) {
            float depth = daccp / wtp;
            if (!isfinite(depth)) depth = ds[wl][ord[wl][95]];
            out[(size_t)NRAY*32 + ray] = depth;
            out[(size_t)NRAY*33 + ray] = wtp;
            out[(size_t)NRAY*34 + ray] = src[wl][95];
        }
    }
}

extern "C" void kernel_launch(void* const* d_in, const int* in_sizes, int n_in,
                              void* d_out, int out_size) {
    const float* planes = (const float*)d_in[0];
    const float* ro     = (const float*)d_in[1];
    const float* rd     = (const float*)d_in[2];
    const float* w1     = (const float*)d_in[3];
    const float* b1     = (const float*)d_in[4];
    const float* w2     = (const float*)d_in[5];
    const float* b2     = (const float*)d_in[6];
    const float* nstrat = (const float*)d_in[7];
    const float* nimp   = (const float*)d_in[8];
    float* out = (float*)d_out;

    k_trans_prep<<<dim3(RES*RES/32 + 1, 1, BB*3), dim3(32, 32)>>>(planes, w1, w2);
    k_eval_m<<<NSAMP/128, 128>>>(ro, rd, b1, b2, nstrat, /*fine=*/0);
    k_importance<<<(NRAY*32)/128, 128>>>(nimp);
    k_eval_m<<<NSAMP/128, 128>>>(ro, rd, b1, b2, nstrat, /*fine=*/1);
    k_final<<<(NRAY*32)/256, 256>>>(out);
}

// round 15
// speedup vs baseline: 1.0092x; 1.0092x over previous
#include <cuda_runtime.h>
#include <cuda_bf16.h>
#include <cuda_fp16.h>
#include <math.h>
#include <stdint.h>

// Problem constants
#define BB   2
#define RR   4096
#define SC   48
#define SFN  48
#define CF   32
#define RES  256
#define HID  64
#define ODIM 33
#define NRAY  (BB*RR)    // 8192
#define NSAMP (NRAY*SC)  // 393216

#define DELTA_F ((2.0f - 0.1f) / (float)(SC - 1))

typedef unsigned long long ull;

__device__ __forceinline__ float softplus_fast(float x) {
    float l = __logf(1.f + __expf(-fabsf(x)));
    return (x > 0.f) ? (x + l) : l;
}

__device__ __forceinline__ uint32_t smem_u32(const void* p) {
    uint32_t a;
    asm("{ .reg .u64 t; cvta.to.shared.u64 t, %1; cvt.u32.u64 %0, t; }" : "=r"(a) : "l"(p));
    return a;
}

// ---- mma / ldmatrix wrappers (base PTX) ----
__device__ __forceinline__ void ldsm_x4(uint32_t& r0, uint32_t& r1, uint32_t& r2, uint32_t& r3, uint32_t addr) {
    asm volatile("ldmatrix.sync.aligned.m8n8.x4.shared.b16 {%0,%1,%2,%3}, [%4];"
        : "=r"(r0), "=r"(r1), "=r"(r2), "=r"(r3) : "r"(addr));
}
__device__ __forceinline__ void mma16816h(float& d0, float& d1, float& d2, float& d3,
                                           uint32_t a0, uint32_t a1, uint32_t a2, uint32_t a3,
                                           uint32_t b0, uint32_t b1) {
    asm volatile("mma.sync.aligned.m16n8k16.row.col.f32.f16.f16.f32 "
        "{%0,%1,%2,%3}, {%4,%5,%6,%7}, {%8,%9}, {%0,%1,%2,%3};"
        : "+f"(d0), "+f"(d1), "+f"(d2), "+f"(d3)
        : "r"(a0), "r"(a1), "r"(a2), "r"(a3), "r"(b0), "r"(b1));
}

__device__ __forceinline__ uint32_t packhf(float lo, float hi) {
    __half2 h2; h2.x = __float2half_rn(lo); h2.y = __float2half_rn(hi);
    return *(uint32_t*)&h2;
}
__device__ __forceinline__ uint32_t hfma2u(uint32_t a, uint32_t b, uint32_t c) {
    __half2 r = __hfma2(*(__half2*)&a, *(__half2*)&b, *(__half2*)&c);
    return *(uint32_t*)&r;
}
__device__ __forceinline__ uint32_t hadd2u(uint32_t a, uint32_t b) {
    __half2 r = __hadd2(*(__half2*)&a, *(__half2*)&b);
    return *(uint32_t*)&r;
}

// -------- device scratch --------
__device__ __half g_planes_h[(size_t)BB*3*RES*RES*CF]; // [b,p,y,x,c] fp16, 25MB
__device__ float g_depths_c[NSAMP];
__device__ float g_depths_f[NSAMP];
__device__ float g_sigma_c[NSAMP];
__device__ float g_sigma_f[NSAMP];
__device__ __half g_rgb_c[(size_t)NSAMP*32];           // fp16 rgb, 24MB
__device__ __half g_rgb_f[(size_t)NSAMP*32];
__device__ uint32_t g_Bt1[64*32];    // 8KB
__device__ uint32_t g_Bt2[40*32];    // 5KB

// -------- merged: transpose planes to fp16 + weight prep --------
__global__ void k_trans_prep(const float* __restrict__ in,
                             const float* __restrict__ w1, const float* __restrict__ w2) {
    if (blockIdx.x == RES*RES/32) {
        if (blockIdx.z != 0) return;
        int t = threadIdx.y*32 + threadIdx.x;
        for (int i = t; i < 64*32; i += 1024) g_Bt1[i] = 0;
        for (int i = t; i < 40*32; i += 1024) g_Bt2[i] = 0;
        __syncthreads();
        for (int e = t; e < 64*32; e += 1024) {
            int n = e >> 5, k = e & 31;
            float v = w1[k*HID + n] * (1.f/3.f);
            uint32_t pos = (uint32_t)n*128u + ((((uint32_t)k >> 3) ^ (n & 7)) << 4) + (k & 7)*2u;
            *(__half*)((char*)g_Bt1 + pos) = __float2half_rn(v);
        }
        for (int e = t; e < 33*64; e += 1024) {
            int n = e >> 6, k = e & 63;
            int out = (n < 32) ? (n + 1) : 0;
            float v = w2[k*ODIM + out];
            uint32_t pos = (uint32_t)n*128u + ((((uint32_t)k >> 3) ^ (n & 7)) << 4) + (k & 7)*2u;
            *(__half*)((char*)g_Bt2 + pos) = __float2half_rn(v);
        }
        return;
    }
    __shared__ float tile[32][33];
    int bp = blockIdx.z;
    int m0 = blockIdx.x * 32;
    int tx = threadIdx.x, ty = threadIdx.y;
    tile[ty][tx] = in[((size_t)bp*CF + ty)*(RES*RES) + m0 + tx];
    __syncthreads();
    g_planes_h[((size_t)bp*(RES*RES) + (m0 + ty))*CF + tx] = __float2half_rn(tile[tx][ty]);
}

// -------- fused eval: precomputed-offset fp16 gather + fp16 mma MLP --------
__global__ void __launch_bounds__(128, 5) k_eval_m(
    const float* __restrict__ ro, const float* __restrict__ rd,
    const float* __restrict__ b1, const float* __restrict__ b2,
    const float* __restrict__ nstrat, int fine)
{
    __shared__ __align__(16) char sA[128*128];    // 16KB
    __shared__ __align__(16) char sB1[64*128];    // 8KB
    __shared__ __align__(16) char sB2[40*128];    // 5KB
    __shared__ uint32_t sOff[6][128];             // 3KB
    __shared__ uint32_t sWgt[6][128];             // 3KB
    __shared__ float sb1[HID];
    __shared__ float sb2p[40];

    int tid = threadIdx.x;
    {
        uint4* d1 = (uint4*)sB1; const uint4* s1 = (const uint4*)g_Bt1;
        for (int i = tid; i < 512; i += 128) d1[i] = s1[i];
        uint4* d2 = (uint4*)sB2; const uint4* s2 = (const uint4*)g_Bt2;
        for (int i = tid; i < 320; i += 128) d2[i] = s2[i];
    }
    if (tid < HID) sb1[tid] = b1[tid];
    if (tid < 40)  sb2p[tid] = (tid < 32) ? b2[tid + 1] : ((tid == 32) ? b2[0] : 0.f);

    int idx = blockIdx.x * 128 + tid;
    float*  sigma_out = fine ? g_sigma_f : g_sigma_c;
    __half* rgb_out   = fine ? g_rgb_f   : g_rgb_c;

    // ---- phase 1: per-sample offsets + corner weights (warp-local consumers) ----
    {
        int ray = idx / SC;
        float t;
        if (fine) {
            t = g_depths_f[idx];
        } else {
            int s = idx % SC;
            t = 0.1f + (float)s * DELTA_F + nstrat[idx] * DELTA_F;
            g_depths_c[idx] = t;
        }
        int bb = (idx >= NSAMP/2) ? 1 : 0;
        float cc[3];
        cc[0] = (ro[ray*3+0] + t*rd[ray*3+0]) * 0.5f;
        cc[1] = (ro[ray*3+1] + t*rd[ray*3+1]) * 0.5f;
        cc[2] = (ro[ray*3+2] + t*rd[ray*3+2]) * 0.5f;
#pragma unroll
        for (int p = 0; p < 3; p++) {
            float x = ((cc[p] + 1.f)*(float)RES - 1.f)*0.5f;
            float y = ((cc[(p+1)%3] + 1.f)*(float)RES - 1.f)*0.5f;
            float x0f = floorf(x), y0f = floorf(y);
            float wx1 = x - x0f, wy1 = y - y0f;
            int x0 = (int)x0f, y0 = (int)y0f;
            int xs = min(max(x0, 0), RES-2);
            float wxc0 = (xs == x0) ? (1.f - wx1) : ((xs == x0+1) ? wx1 : 0.f);
            float wxc1 = (xs+1 == x0) ? (1.f - wx1) : ((xs+1 == x0+1) ? wx1 : 0.f);
            uint32_t pb = (uint32_t)(bb*3 + p) * (RES*RES*CF*2u);
#pragma unroll
            for (int cy = 0; cy < 2; cy++) {
                int yy = y0 + cy;
                float wyv = cy ? wy1 : (1.f - wy1);
                if (yy < 0 || yy >= RES) wyv = 0.f;
                int yyc = min(max(yy, 0), RES-1);
                sOff[p*2+cy][tid] = pb + (uint32_t)(yyc*RES + xs) * (CF*2u);
                sWgt[p*2+cy][tid] = packhf(wxc0*wyv, wxc1*wyv);
            }
        }
    }
    __syncwarp();   // warp-local consumers only

    int wid = tid >> 5, l = tid & 31;

    // ---- phase 2: cooperative gather, single 6-load batch ----
    {
        int bcorner = (l >> 2) & 1;
        int cb = l & 3;
        uint32_t lane_byte = (uint32_t)(l & 7) * 16u;
        const char* pbase = (const char*)g_planes_h;
#pragma unroll 1
        for (int g = 0; g < 8; g++) {
            int s_loc = wid*32 + g*4 + (l >> 3);

            uint32_t wu[6];
            const uint4* addr[6];
#pragma unroll
            for (int j = 0; j < 6; j++) {
                uint32_t off = sOff[j][s_loc];
                uint32_t w2 = sWgt[j][s_loc];
                uint32_t h = bcorner ? (w2 >> 16) : (w2 & 0xFFFFu);
                wu[j] = h | (h << 16);
                addr[j] = (const uint4*)(pbase + off + lane_byte);
            }
            uint4 v[6];
#pragma unroll
            for (int j = 0; j < 6; j++) v[j] = *addr[j];

            uint32_t acc[4] = {0u, 0u, 0u, 0u};
#pragma unroll
            for (int j = 0; j < 6; j++) {
                const uint32_t* hp = (const uint32_t*)&v[j];
#pragma unroll
                for (int h = 0; h < 4; h++)
                    acc[h] = hfma2u(wu[j], hp[h], acc[h]);
            }
#pragma unroll
            for (int h = 0; h < 4; h++) {
                uint32_t other = __shfl_xor_sync(0xFFFFFFFFu, acc[h], 4);
                acc[h] = hadd2u(acc[h], other);
            }
            if (!(l & 4)) {
                uint32_t rb = (uint32_t)s_loc * 128u;
                uint32_t sw = (uint32_t)(s_loc & 7);
                *(uint4*)(sA + rb + ((((uint32_t)cb) ^ sw) << 4)) = make_uint4(acc[0], acc[1], acc[2], acc[3]);
            }
        }
    }
    __syncthreads();   // B-tiles + cross-warp sA visibility before ldsm

    uint32_t aBase  = smem_u32(sA);
    uint32_t b1Base = smem_u32(sB1);
    uint32_t b2Base = smem_u32(sB2);

    int lq = l >> 2;
    int lr2 = (l & 3) * 2;

#pragma unroll
    for (int m = 0; m < 2; m++) {
        int R = wid*32 + m*16;

        uint32_t af[2][4];
        {
            int arow = R + (l & 7) + 8*((l >> 3) & 1);
            uint32_t aseg = (uint32_t)(l >> 4);
            uint32_t rb = (uint32_t)arow * 128u;
            uint32_t sw = (uint32_t)(arow & 7);
#pragma unroll
            for (int kt = 0; kt < 2; kt++) {
                uint32_t addr = aBase + rb + ((((uint32_t)kt*2u + aseg) ^ sw) << 4);
                ldsm_x4(af[kt][0], af[kt][1], af[kt][2], af[kt][3], addr);
            }
        }

        // layer 1: D = a * W (K=32)
        uint32_t a2f[4][4];
        {
            int brow = (l & 7);
            uint32_t bchunk = (uint32_t)(l >> 3);
#pragma unroll
            for (int nt = 0; nt < 8; nt++) {
                int bn = nt*8 + brow;
                uint32_t brb = (uint32_t)bn * 128u;
                uint32_t bsw = (uint32_t)(bn & 7);
                uint32_t hA0, hA1, hB0, hB1;
                ldsm_x4(hA0, hA1, hB0, hB1, b1Base + brb + ((bchunk ^ bsw) << 4));
                float d0 = 0.f, d1 = 0.f, d2 = 0.f, d3 = 0.f;
                mma16816h(d0,d1,d2,d3, af[0][0],af[0][1],af[0][2],af[0][3], hA0,hA1);
                mma16816h(d0,d1,d2,d3, af[1][0],af[1][1],af[1][2],af[1][3], hB0,hB1);

                int col0 = nt*8 + lr2;
                float s0 = softplus_fast(d0 + sb1[col0]);
                float s1 = softplus_fast(d1 + sb1[col0+1]);
                float s2 = softplus_fast(d2 + sb1[col0]);
                float s3 = softplus_fast(d3 + sb1[col0+1]);
                int kk = nt >> 1, half = nt & 1;
                a2f[kk][2*half+0] = packhf(s0, s1);
                a2f[kk][2*half+1] = packhf(s2, s3);
            }
        }

        // layer 2: D = h * W (K=64) ; N=40 permuted
        {
            int brow = (l & 7);
            uint32_t bchunk = (uint32_t)(l >> 3);
            int r0 = blockIdx.x*128 + R + lq;
            int r1 = r0 + 8;
#pragma unroll
            for (int nt2 = 0; nt2 < 5; nt2++) {
                int bn = nt2*8 + brow;
                uint32_t brb = (uint32_t)bn * 128u;
                uint32_t bsw = (uint32_t)(bn & 7);
                uint32_t e0r[4], e1r[4];
                ldsm_x4(e0r[0], e0r[1], e0r[2], e0r[3], b2Base + brb + (((bchunk      ) ^ bsw) << 4));
                ldsm_x4(e1r[0], e1r[1], e1r[2], e1r[3], b2Base + brb + (((4u + bchunk) ^ bsw) << 4));

                float d0 = 0.f, d1 = 0.f, d2 = 0.f, d3 = 0.f;
                mma16816h(d0,d1,d2,d3, a2f[0][0],a2f[0][1],a2f[0][2],a2f[0][3], e0r[0],e0r[1]);
                mma16816h(d0,d1,d2,d3, a2f[1][0],a2f[1][1],a2f[1][2],a2f[1][3], e0r[2],e0r[3]);
                mma16816h(d0,d1,d2,d3, a2f[2][0],a2f[2][1],a2f[2][2],a2f[2][3], e1r[0],e1r[1]);
                mma16816h(d0,d1,d2,d3, a2f[3][0],a2f[3][1],a2f[3][2],a2f[3][3], e1r[2],e1r[3]);

                int col0 = nt2*8 + lr2;
                if (nt2 < 4) {
                    float v0 = __fdividef(1.002f, 1.f + __expf(-(d0 + sb2p[col0])))   - 0.001f;
                    float v1 = __fdividef(1.002f, 1.f + __expf(-(d1 + sb2p[col0+1]))) - 0.001f;
                    float v2 = __fdividef(1.002f, 1.f + __expf(-(d2 + sb2p[col0])))   - 0.001f;
                    float v3 = __fdividef(1.002f, 1.f + __expf(-(d3 + sb2p[col0+1]))) - 0.001f;
                    *(uint32_t*)&rgb_out[(size_t)r0*32 + col0] = packhf(v0, v1);
                    *(uint32_t*)&rgb_out[(size_t)r1*32 + col0] = packhf(v2, v3);
                } else if (lr2 == 0) {
                    sigma_out[r0] = d0 + sb2p[32];
                    sigma_out[r1] = d2 + sb2p[32];
                }
            }
        }
    }
}

// -------- warp-per-ray: coarse march weights + inverse-CDF sampling --------
__global__ void __launch_bounds__(128, 8) k_importance(const float* __restrict__ nimp) {
    int gw   = (blockIdx.x * 128 + threadIdx.x) >> 5;
    int lane = threadIdx.x & 31;
    int wl   = threadIdx.x >> 5;
    __shared__ float sh_d[4][48], sh_s[4][48];
    __shared__ float sh_a[4][48];
    __shared__ float sh_w[4][48];
    __shared__ float sh_cdf[4][46];
    __shared__ float sh_bins[4][48];
    if (gw >= NRAY) return;

    const float* dp = g_depths_c + (size_t)gw*SC;
    const float* sp = g_sigma_c  + (size_t)gw*SC;
    for (int i = lane; i < 48; i += 32) { sh_d[wl][i] = dp[i]; sh_s[wl][i] = sp[i]; }
    __syncwarp();

    for (int i = lane; i < 47; i += 32) {
        float d0 = sh_d[wl][i], d1 = sh_d[wl][i+1];
        float dens = softplus_fast(0.5f*(sh_s[wl][i] + sh_s[wl][i+1]) - 1.f);
        sh_a[wl][i]    = 1.f - __expf(-dens*(d1 - d0));
        sh_bins[wl][i] = 0.5f*(d0 + d1);
    }
    __syncwarp();

    if (lane == 0) {
        float T = 1.f;
        for (int i = 0; i < 47; i++) {
            float a = sh_a[wl][i];
            sh_w[wl][i] = a * T;
            T *= (1.f - a + 1e-10f);
        }
    }
    __syncwarp();

    for (int j = lane; j < 45; j += 32) {
        float m1 = fmaxf(sh_w[wl][j],   sh_w[wl][j+1]);
        float m2 = fmaxf(sh_w[wl][j+1], sh_w[wl][j+2]);
        sh_a[wl][j] = 0.5f*(m1 + m2) + 0.01f + 1e-5f;
    }
    __syncwarp();

    if (lane == 0) {
        float c = 0.f;
        sh_cdf[wl][0] = 0.f;
        for (int j = 0; j < 45; j++) { c += sh_a[wl][j]; sh_cdf[wl][j+1] = c; }
        sh_w[wl][47] = c;
    }
    __syncwarp();
    float inv = __fdividef(1.f, sh_w[wl][47]);
    for (int j = lane + 1; j < 46; j += 32) sh_cdf[wl][j] *= inv;
    __syncwarp();

    const float* up = nimp + (size_t)gw*SFN;
    float* outp = g_depths_f + (size_t)gw*SFN;
    for (int j = lane; j < SFN; j += 32) {
        float u = up[j];
        int ind = 0;
#pragma unroll
        for (int t2 = 0; t2 < 46; t2++) ind += (sh_cdf[wl][t2] <= u) ? 1 : 0;
        int below = ind - 1; if (below < 0) below = 0;
        int above = ind;     if (above > 45) above = 45;
        float cb = sh_cdf[wl][below], ca = sh_cdf[wl][above];
        float bb = sh_bins[wl][below], ba = sh_bins[wl][above];
        float den = ca - cb; if (den < 1e-5f) den = 1.f;
        outp[j] = bb + (u - cb)/den * (ba - bb);
    }
}

// -------- merge, sort, scan-based ray march, outputs --------
__global__ void __launch_bounds__(256) k_final(float* __restrict__ out) {
    int warp = (blockIdx.x * blockDim.x + threadIdx.x) >> 5;
    int lane = threadIdx.x & 31;
    int wl   = threadIdx.x >> 5;
    __shared__ float ds[8][96];
    __shared__ float ss[8][96];
    __shared__ int   ord[8][96];
    __shared__ float scanA[8][96];
    __shared__ float scanB[8][96];
    __shared__ float sal[8][96];
    __shared__ float sdm[8][96];
    __shared__ float swt[8][97];
    if (warp >= NRAY) return;
    int ray = warp;

    for (int k = lane; k < 96; k += 32) {
        float dv, sv;
        if (k < SC) { dv = g_depths_c[(size_t)ray*SC + k]; sv = g_sigma_c[(size_t)ray*SC + k]; }
        else        { dv = g_depths_f[(size_t)ray*SFN + k - SC]; sv = g_sigma_f[(size_t)ray*SFN + k - SC]; }
        ds[wl][k] = dv; ss[wl][k] = sv;
    }
    __syncwarp();

    for (int k = lane; k < 96; k += 32) {
        float di = ds[wl][k];
        int r = 0;
        for (int j = 0; j < 96; j++) {
            float dj = ds[wl][j];
            r += (dj < di) || (dj == di && j < k);
        }
        ord[wl][r] = k;
    }
    __syncwarp();

#pragma unroll
    for (int sblk = 0; sblk < 3; sblk++) {
        int i = lane + sblk*32;
        if (i == 0) {
            scanA[wl][0] = 1.f;
            sal[wl][0] = 0.f;
            sdm[wl][0] = 0.f;
        } else {
            int ip = ord[wl][i-1], ic = ord[wl][i];
            float d0 = ds[wl][ip], d1 = ds[wl][ic];
            float s0 = ss[wl][ip], s1 = ss[wl][ic];
            float dens  = softplus_fast(0.5f*(s0 + s1) - 1.f);
            float alpha = 1.f - __expf(-dens*(d1 - d0));
            scanA[wl][i] = 1.f - alpha + 1e-10f;
            sal[wl][i] = alpha;
            sdm[wl][i] = 0.5f*(d0 + d1);
        }
    }
    __syncwarp();

    {
        float (*src)[96] = scanA; float (*dst)[96] = scanB;
#pragma unroll
        for (int dstep = 1; dstep < 96; dstep <<= 1) {
#pragma unroll
            for (int sblk = 0; sblk < 3; sblk++) {
                int s = lane + sblk*32;
                float v = src[wl][s];
                if (s >= dstep) v *= src[wl][s - dstep];
                dst[wl][s] = v;
            }
            __syncwarp();
            float (*tmp)[96] = src; src = dst; dst = tmp;
        }
#pragma unroll
        for (int sblk = 0; sblk < 3; sblk++) {
            int i = lane + sblk*32;
            swt[wl][i] = (i >= 1) ? sal[wl][i] * src[wl][i-1] : 0.f;
        }
        if (lane == 0) swt[wl][96] = 0.f;
        __syncwarp();

        float wtp = 0.f, daccp = 0.f;
#pragma unroll
        for (int sblk = 0; sblk < 3; sblk++) {
            int i = lane + sblk*32;
            float w = swt[wl][i];
            wtp += w;
            daccp += w * sdm[wl][i];
            sal[wl][ord[wl][i]] = 0.5f*(swt[wl][i] + swt[wl][i+1]);
        }
        __syncwarp();
#pragma unroll
        for (int o = 16; o > 0; o >>= 1) {
            wtp   += __shfl_xor_sync(0xFFFFFFFFu, wtp, o);
            daccp += __shfl_xor_sync(0xFFFFFFFFu, daccp, o);
        }

        float acc = 0.f;
        const __half* pc = g_rgb_c + (size_t)ray*SC*32 + lane;
        const __half* pf = g_rgb_f + (size_t)ray*SFN*32 + lane;
#pragma unroll 8
        for (int k = 0; k < 48; k++) acc += sal[wl][k] * __half2float(pc[(size_t)k*32]);
#pragma unroll 8
        for (int k = 0; k < 48; k++) acc += sal[wl][48+k] * __half2float(pf[(size_t)k*32]);

        out[(size_t)ray*32 + lane] = acc*2.f - 1.f;
        if (lane == 0) {
            float depth = daccp / wtp;
            if (!isfinite(depth)) depth = ds[wl][ord[wl][95]];
            out[(size_t)NRAY*32 + ray] = depth;
            out[(size_t)NRAY*33 + ray] = wtp;
            out[(size_t)NRAY*34 + ray] = src[wl][95];
        }
    }
}

extern "C" void kernel_launch(void* const* d_in, const int* in_sizes, int n_in,
                              void* d_out, int out_size) {
    const float* planes = (const float*)d_in[0];
    const float* ro     = (const float*)d_in[1];
    const float* rd     = (const float*)d_in[2];
    const float* w1     = (const float*)d_in[3];
    const float* b1     = (const float*)d_in[4];
    const float* w2     = (const float*)d_in[5];
    const float* b2     = (const float*)d_in[6];
    const float* nstrat = (const float*)d_in[7];
    const float* nimp   = (const float*)d_in[8];
    float* out = (float*)d_out;

    k_trans_prep<<<dim3(RES*RES/32 + 1, 1, BB*3), dim3(32, 32)>>>(planes, w1, w2);
    k_eval_m<<<NSAMP/128, 128>>>(ro, rd, b1, b2, nstrat, /*fine=*/0);
    k_importance<<<(NRAY*32)/128, 128>>>(nimp);
    k_eval_m<<<NSAMP/128, 128>>>(ro, rd, b1, b2, nstrat, /*fine=*/1);
    k_final<<<(NRAY*32)/256, 256>>>(out);
}

// round 16
// speedup vs baseline: 1.1730x; 1.1623x over previous
#include <cuda_runtime.h>
#include <cuda_bf16.h>
#include <cuda_fp16.h>
#include <math.h>
#include <stdint.h>

// Problem constants
#define BB   2
#define RR   4096
#define SC   48
#define SFN  48
#define CF   32
#define RES  256
#define HID  64
#define ODIM 33
#define NRAY  (BB*RR)    // 8192
#define NSAMP (NRAY*SC)  // 393216

#define DELTA_F ((2.0f - 0.1f) / (float)(SC - 1))

typedef unsigned long long ull;

__device__ __forceinline__ float softplus_fast(float x) {
    float l = __logf(1.f + __expf(-fabsf(x)));
    return (x > 0.f) ? (x + l) : l;
}

__device__ __forceinline__ uint32_t smem_u32(const void* p) {
    uint32_t a;
    asm("{ .reg .u64 t; cvta.to.shared.u64 t, %1; cvt.u32.u64 %0, t; }" : "=r"(a) : "l"(p));
    return a;
}

// ---- mma / ldmatrix wrappers (base PTX) ----
__device__ __forceinline__ void ldsm_x4(uint32_t& r0, uint32_t& r1, uint32_t& r2, uint32_t& r3, uint32_t addr) {
    asm volatile("ldmatrix.sync.aligned.m8n8.x4.shared.b16 {%0,%1,%2,%3}, [%4];"
        : "=r"(r0), "=r"(r1), "=r"(r2), "=r"(r3) : "r"(addr));
}
__device__ __forceinline__ void mma16816h(float& d0, float& d1, float& d2, float& d3,
                                           uint32_t a0, uint32_t a1, uint32_t a2, uint32_t a3,
                                           uint32_t b0, uint32_t b1) {
    asm volatile("mma.sync.aligned.m16n8k16.row.col.f32.f16.f16.f32 "
        "{%0,%1,%2,%3}, {%4,%5,%6,%7}, {%8,%9}, {%0,%1,%2,%3};"
        : "+f"(d0), "+f"(d1), "+f"(d2), "+f"(d3)
        : "r"(a0), "r"(a1), "r"(a2), "r"(a3), "r"(b0), "r"(b1));
}

__device__ __forceinline__ uint32_t packhf(float lo, float hi) {
    __half2 h2; h2.x = __float2half_rn(lo); h2.y = __float2half_rn(hi);
    return *(uint32_t*)&h2;
}
__device__ __forceinline__ uint32_t hfma2u(uint32_t a, uint32_t b, uint32_t c) {
    __half2 r = __hfma2(*(__half2*)&a, *(__half2*)&b, *(__half2*)&c);
    return *(uint32_t*)&r;
}
__device__ __forceinline__ uint32_t hadd2u(uint32_t a, uint32_t b) {
    __half2 r = __hadd2(*(__half2*)&a, *(__half2*)&b);
    return *(uint32_t*)&r;
}

// -------- device scratch --------
__device__ __half g_planes_h[(size_t)BB*3*RES*RES*CF]; // [b,p,y,x,c] fp16, 25MB
__device__ float g_depths_c[NSAMP];
__device__ float g_depths_f[NSAMP];
__device__ float g_sigma_c[NSAMP];
__device__ float g_sigma_f[NSAMP];
__device__ __half g_rgb_c[(size_t)NSAMP*32];           // fp16 rgb, 24MB
__device__ __half g_rgb_f[(size_t)NSAMP*32];
__device__ uint32_t g_Bt1[64*32];    // 8KB
__device__ uint32_t g_Bt2[40*32];    // 5KB

// -------- merged: transpose planes to fp16 (4 m/thread) + weight prep --------
__global__ void k_trans_prep(const float* __restrict__ in,
                             const float* __restrict__ w1, const float* __restrict__ w2) {
    if (blockIdx.x == RES*RES/128) {
        if (blockIdx.z != 0) return;
        int t = threadIdx.y*32 + threadIdx.x;
        for (int i = t; i < 64*32; i += 1024) g_Bt1[i] = 0;
        for (int i = t; i < 40*32; i += 1024) g_Bt2[i] = 0;
        __syncthreads();
        for (int e = t; e < 64*32; e += 1024) {
            int n = e >> 5, k = e & 31;
            float v = w1[k*HID + n] * (1.f/3.f);
            uint32_t pos = (uint32_t)n*128u + ((((uint32_t)k >> 3) ^ (n & 7)) << 4) + (k & 7)*2u;
            *(__half*)((char*)g_Bt1 + pos) = __float2half_rn(v);
        }
        for (int e = t; e < 33*64; e += 1024) {
            int n = e >> 6, k = e & 63;
            int out = (n < 32) ? (n + 1) : 0;
            float v = w2[k*ODIM + out];
            uint32_t pos = (uint32_t)n*128u + ((((uint32_t)k >> 3) ^ (n & 7)) << 4) + (k & 7)*2u;
            *(__half*)((char*)g_Bt2 + pos) = __float2half_rn(v);
        }
        return;
    }
    __shared__ float tile[32][129];      // [channel][m'] padded: transposed read conflict-free
    int bp = blockIdx.z;
    int m0 = blockIdx.x * 128;
    int tx = threadIdx.x, ty = threadIdx.y;
    const float* src = in + ((size_t)bp*CF + ty)*(RES*RES) + m0;
#pragma unroll
    for (int q = 0; q < 4; q++)
        tile[ty][tx + 32*q] = src[tx + 32*q];
    __syncthreads();
    __half* dst = g_planes_h + ((size_t)bp*(RES*RES) + m0)*CF;
#pragma unroll
    for (int q = 0; q < 4; q++) {
        int mm = ty*4 + q;
        dst[(size_t)mm*CF + tx] = __float2half_rn(tile[tx][mm]);
    }
}

// -------- fused eval: warp-independent phases, single early barrier --------
__global__ void __launch_bounds__(128, 5) k_eval_m(
    const float* __restrict__ ro, const float* __restrict__ rd,
    const float* __restrict__ b1, const float* __restrict__ b2,
    const float* __restrict__ nstrat, int fine)
{
    __shared__ __align__(16) char sA[128*128];    // 16KB (warp-local rows)
    __shared__ __align__(16) char sB1[64*128];    // 8KB
    __shared__ __align__(16) char sB2[40*128];    // 5KB
    __shared__ uint32_t sOff[6][128];             // 3KB (warp-local)
    __shared__ uint32_t sWgt[6][128];             // 3KB (warp-local)
    __shared__ float sb1[HID];
    __shared__ float sb2p[40];

    int tid = threadIdx.x;
    {
        uint4* d1 = (uint4*)sB1; const uint4* s1 = (const uint4*)g_Bt1;
        for (int i = tid; i < 512; i += 128) d1[i] = s1[i];
        uint4* d2 = (uint4*)sB2; const uint4* s2 = (const uint4*)g_Bt2;
        for (int i = tid; i < 320; i += 128) d2[i] = s2[i];
    }
    if (tid < HID) sb1[tid] = b1[tid];
    if (tid < 40)  sb2p[tid] = (tid < 32) ? b2[tid + 1] : ((tid == 32) ? b2[0] : 0.f);
    __syncthreads();   // ONE block barrier: B tiles + biases visible; all later smem is warp-local

    int idx = blockIdx.x * 128 + tid;
    float*  sigma_out = fine ? g_sigma_f : g_sigma_c;
    __half* rgb_out   = fine ? g_rgb_f   : g_rgb_c;

    // ---- phase 1: per-sample offsets + corner weights ----
    {
        int ray = idx / SC;
        float t;
        if (fine) {
            t = g_depths_f[idx];
        } else {
            int s = idx % SC;
            t = 0.1f + (float)s * DELTA_F + nstrat[idx] * DELTA_F;
            g_depths_c[idx] = t;
        }
        int bb = (idx >= NSAMP/2) ? 1 : 0;
        float cc[3];
        cc[0] = (ro[ray*3+0] + t*rd[ray*3+0]) * 0.5f;
        cc[1] = (ro[ray*3+1] + t*rd[ray*3+1]) * 0.5f;
        cc[2] = (ro[ray*3+2] + t*rd[ray*3+2]) * 0.5f;
#pragma unroll
        for (int p = 0; p < 3; p++) {
            float x = ((cc[p] + 1.f)*(float)RES - 1.f)*0.5f;
            float y = ((cc[(p+1)%3] + 1.f)*(float)RES - 1.f)*0.5f;
            float x0f = floorf(x), y0f = floorf(y);
            float wx1 = x - x0f, wy1 = y - y0f;
            int x0 = (int)x0f, y0 = (int)y0f;
            int xs = min(max(x0, 0), RES-2);
            float wxc0 = (xs == x0) ? (1.f - wx1) : ((xs == x0+1) ? wx1 : 0.f);
            float wxc1 = (xs+1 == x0) ? (1.f - wx1) : ((xs+1 == x0+1) ? wx1 : 0.f);
            uint32_t pb = (uint32_t)(bb*3 + p) * (RES*RES*CF*2u);
#pragma unroll
            for (int cy = 0; cy < 2; cy++) {
                int yy = y0 + cy;
                float wyv = cy ? wy1 : (1.f - wy1);
                if (yy < 0 || yy >= RES) wyv = 0.f;
                int yyc = min(max(yy, 0), RES-1);
                sOff[p*2+cy][tid] = pb + (uint32_t)(yyc*RES + xs) * (CF*2u);
                sWgt[p*2+cy][tid] = packhf(wxc0*wyv, wxc1*wyv);
            }
        }
    }
    __syncwarp();

    int wid = tid >> 5, l = tid & 31;

    // ---- phase 2: cooperative gather (warp-local) ----
    {
        int bcorner = (l >> 2) & 1;
        int cb = l & 3;
        uint32_t lane_byte = (uint32_t)(l & 7) * 16u;
        const char* pbase = (const char*)g_planes_h;
#pragma unroll 1
        for (int g = 0; g < 8; g++) {
            int s_loc = wid*32 + g*4 + (l >> 3);

            uint32_t wu[6];
            const uint4* addr[6];
#pragma unroll
            for (int j = 0; j < 6; j++) {
                uint32_t off = sOff[j][s_loc];
                uint32_t w2 = sWgt[j][s_loc];
                uint32_t h = bcorner ? (w2 >> 16) : (w2 & 0xFFFFu);
                wu[j] = h | (h << 16);
                addr[j] = (const uint4*)(pbase + off + lane_byte);
            }
            uint4 v[6];
#pragma unroll
            for (int j = 0; j < 6; j++) v[j] = *addr[j];

            uint32_t acc[4] = {0u, 0u, 0u, 0u};
#pragma unroll
            for (int j = 0; j < 6; j++) {
                const uint32_t* hp = (const uint32_t*)&v[j];
#pragma unroll
                for (int h = 0; h < 4; h++)
                    acc[h] = hfma2u(wu[j], hp[h], acc[h]);
            }
#pragma unroll
            for (int h = 0; h < 4; h++) {
                uint32_t other = __shfl_xor_sync(0xFFFFFFFFu, acc[h], 4);
                acc[h] = hadd2u(acc[h], other);
            }
            if (!(l & 4)) {
                uint32_t rb = (uint32_t)s_loc * 128u;
                uint32_t sw = (uint32_t)(s_loc & 7);
                *(uint4*)(sA + rb + ((((uint32_t)cb) ^ sw) << 4)) = make_uint4(acc[0], acc[1], acc[2], acc[3]);
            }
        }
    }
    __syncwarp();   // sA rows consumed below are written by THIS warp only

    uint32_t aBase  = smem_u32(sA);
    uint32_t b1Base = smem_u32(sB1);
    uint32_t b2Base = smem_u32(sB2);

    int lq = l >> 2;
    int lr2 = (l & 3) * 2;

#pragma unroll
    for (int m = 0; m < 2; m++) {
        int R = wid*32 + m*16;

        uint32_t af[2][4];
        {
            int arow = R + (l & 7) + 8*((l >> 3) & 1);
            uint32_t aseg = (uint32_t)(l >> 4);
            uint32_t rb = (uint32_t)arow * 128u;
            uint32_t sw = (uint32_t)(arow & 7);
#pragma unroll
            for (int kt = 0; kt < 2; kt++) {
                uint32_t addr = aBase + rb + ((((uint32_t)kt*2u + aseg) ^ sw) << 4);
                ldsm_x4(af[kt][0], af[kt][1], af[kt][2], af[kt][3], addr);
            }
        }

        // layer 1: D = a * W (K=32)
        uint32_t a2f[4][4];
        {
            int brow = (l & 7);
            uint32_t bchunk = (uint32_t)(l >> 3);
#pragma unroll
            for (int nt = 0; nt < 8; nt++) {
                int bn = nt*8 + brow;
                uint32_t brb = (uint32_t)bn * 128u;
                uint32_t bsw = (uint32_t)(bn & 7);
                uint32_t hA0, hA1, hB0, hB1;
                ldsm_x4(hA0, hA1, hB0, hB1, b1Base + brb + ((bchunk ^ bsw) << 4));
                float d0 = 0.f, d1 = 0.f, d2 = 0.f, d3 = 0.f;
                mma16816h(d0,d1,d2,d3, af[0][0],af[0][1],af[0][2],af[0][3], hA0,hA1);
                mma16816h(d0,d1,d2,d3, af[1][0],af[1][1],af[1][2],af[1][3], hB0,hB1);

                int col0 = nt*8 + lr2;
                float s0 = softplus_fast(d0 + sb1[col0]);
                float s1 = softplus_fast(d1 + sb1[col0+1]);
                float s2 = softplus_fast(d2 + sb1[col0]);
                float s3 = softplus_fast(d3 + sb1[col0+1]);
                int kk = nt >> 1, half = nt & 1;
                a2f[kk][2*half+0] = packhf(s0, s1);
                a2f[kk][2*half+1] = packhf(s2, s3);
            }
        }

        // layer 2: D = h * W (K=64) ; N=40 permuted
        {
            int brow = (l & 7);
            uint32_t bchunk = (uint32_t)(l >> 3);
            int r0 = blockIdx.x*128 + R + lq;
            int r1 = r0 + 8;
#pragma unroll
            for (int nt2 = 0; nt2 < 5; nt2++) {
                int bn = nt2*8 + brow;
                uint32_t brb = (uint32_t)bn * 128u;
                uint32_t bsw = (uint32_t)(bn & 7);
                uint32_t e0r[4], e1r[4];
                ldsm_x4(e0r[0], e0r[1], e0r[2], e0r[3], b2Base + brb + (((bchunk      ) ^ bsw) << 4));
                ldsm_x4(e1r[0], e1r[1], e1r[2], e1r[3], b2Base + brb + (((4u + bchunk) ^ bsw) << 4));

                float d0 = 0.f, d1 = 0.f, d2 = 0.f, d3 = 0.f;
                mma16816h(d0,d1,d2,d3, a2f[0][0],a2f[0][1],a2f[0][2],a2f[0][3], e0r[0],e0r[1]);
                mma16816h(d0,d1,d2,d3, a2f[1][0],a2f[1][1],a2f[1][2],a2f[1][3], e0r[2],e0r[3]);
                mma16816h(d0,d1,d2,d3, a2f[2][0],a2f[2][1],a2f[2][2],a2f[2][3], e1r[0],e1r[1]);
                mma16816h(d0,d1,d2,d3, a2f[3][0],a2f[3][1],a2f[3][2],a2f[3][3], e1r[2],e1r[3]);

                int col0 = nt2*8 + lr2;
                if (nt2 < 4) {
                    float v0 = __fdividef(1.002f, 1.f + __expf(-(d0 + sb2p[col0])))   - 0.001f;
                    float v1 = __fdividef(1.002f, 1.f + __expf(-(d1 + sb2p[col0+1]))) - 0.001f;
                    float v2 = __fdividef(1.002f, 1.f + __expf(-(d2 + sb2p[col0])))   - 0.001f;
                    float v3 = __fdividef(1.002f, 1.f + __expf(-(d3 + sb2p[col0+1]))) - 0.001f;
                    *(uint32_t*)&rgb_out[(size_t)r0*32 + col0] = packhf(v0, v1);
                    *(uint32_t*)&rgb_out[(size_t)r1*32 + col0] = packhf(v2, v3);
                } else if (lr2 == 0) {
                    sigma_out[r0] = d0 + sb2p[32];
                    sigma_out[r1] = d2 + sb2p[32];
                }
            }
        }
    }
}

// -------- warp-per-ray: coarse march weights + inverse-CDF sampling --------
__global__ void __launch_bounds__(128, 8) k_importance(const float* __restrict__ nimp) {
    int gw   = (blockIdx.x * 128 + threadIdx.x) >> 5;
    int lane = threadIdx.x & 31;
    int wl   = threadIdx.x >> 5;
    __shared__ float sh_d[4][48], sh_s[4][48];
    __shared__ float sh_a[4][48];
    __shared__ float sh_w[4][48];
    __shared__ float sh_cdf[4][46];
    __shared__ float sh_bins[4][48];
    if (gw >= NRAY) return;

    const float* dp = g_depths_c + (size_t)gw*SC;
    const float* sp = g_sigma_c  + (size_t)gw*SC;
    for (int i = lane; i < 48; i += 32) { sh_d[wl][i] = dp[i]; sh_s[wl][i] = sp[i]; }
    __syncwarp();

    for (int i = lane; i < 47; i += 32) {
        float d0 = sh_d[wl][i], d1 = sh_d[wl][i+1];
        float dens = softplus_fast(0.5f*(sh_s[wl][i] + sh_s[wl][i+1]) - 1.f);
        sh_a[wl][i]    = 1.f - __expf(-dens*(d1 - d0));
        sh_bins[wl][i] = 0.5f*(d0 + d1);
    }
    __syncwarp();

    if (lane == 0) {
        float T = 1.f;
        for (int i = 0; i < 47; i++) {
            float a = sh_a[wl][i];
            sh_w[wl][i] = a * T;
            T *= (1.f - a + 1e-10f);
        }
    }
    __syncwarp();

    for (int j = lane; j < 45; j += 32) {
        float m1 = fmaxf(sh_w[wl][j],   sh_w[wl][j+1]);
        float m2 = fmaxf(sh_w[wl][j+1], sh_w[wl][j+2]);
        sh_a[wl][j] = 0.5f*(m1 + m2) + 0.01f + 1e-5f;
    }
    __syncwarp();

    if (lane == 0) {
        float c = 0.f;
        sh_cdf[wl][0] = 0.f;
        for (int j = 0; j < 45; j++) { c += sh_a[wl][j]; sh_cdf[wl][j+1] = c; }
        sh_w[wl][47] = c;
    }
    __syncwarp();
    float inv = __fdividef(1.f, sh_w[wl][47]);
    for (int j = lane + 1; j < 46; j += 32) sh_cdf[wl][j] *= inv;
    __syncwarp();

    const float* up = nimp + (size_t)gw*SFN;
    float* outp = g_depths_f + (size_t)gw*SFN;
    for (int j = lane; j < SFN; j += 32) {
        float u = up[j];
        int ind = 0;
#pragma unroll
        for (int t2 = 0; t2 < 46; t2++) ind += (sh_cdf[wl][t2] <= u) ? 1 : 0;
        int below = ind - 1; if (below < 0) below = 0;
        int above = ind;     if (above > 45) above = 45;
        float cb = sh_cdf[wl][below], ca = sh_cdf[wl][above];
        float bb = sh_bins[wl][below], ba = sh_bins[wl][above];
        float den = ca - cb; if (den < 1e-5f) den = 1.f;
        outp[j] = bb + (u - cb)/den * (ba - bb);
    }
}

// -------- merge, sort, scan-based ray march, outputs --------
__global__ void __launch_bounds__(256) k_final(float* __restrict__ out) {
    int warp = (blockIdx.x * blockDim.x + threadIdx.x) >> 5;
    int lane = threadIdx.x & 31;
    int wl   = threadIdx.x >> 5;
    __shared__ float ds[8][96];
    __shared__ float ss[8][96];
    __shared__ int   ord[8][96];
    __shared__ float scanA[8][96];
    __shared__ float scanB[8][96];
    __shared__ float sal[8][96];
    __shared__ float sdm[8][96];
    __shared__ float swt[8][97];
    if (warp >= NRAY) return;
    int ray = warp;

    for (int k = lane; k < 96; k += 32) {
        float dv, sv;
        if (k < SC) { dv = g_depths_c[(size_t)ray*SC + k]; sv = g_sigma_c[(size_t)ray*SC + k]; }
        else        { dv = g_depths_f[(size_t)ray*SFN + k - SC]; sv = g_sigma_f[(size_t)ray*SFN + k - SC]; }
        ds[wl][k] = dv; ss[wl][k] = sv;
    }
    __syncwarp();

    for (int k = lane; k < 96; k += 32) {
        float di = ds[wl][k];
        int r = 0;
        for (int j = 0; j < 96; j++) {
            float dj = ds[wl][j];
            r += (dj < di) || (dj == di && j < k);
        }
        ord[wl][r] = k;
    }
    __syncwarp();

#pragma unroll
    for (int sblk = 0; sblk < 3; sblk++) {
        int i = lane + sblk*32;
        if (i == 0) {
            scanA[wl][0] = 1.f;
            sal[wl][0] = 0.f;
            sdm[wl][0] = 0.f;
        } else {
            int ip = ord[wl][i-1], ic = ord[wl][i];
            float d0 = ds[wl][ip], d1 = ds[wl][ic];
            float s0 = ss[wl][ip], s1 = ss[wl][ic];
            float dens  = softplus_fast(0.5f*(s0 + s1) - 1.f);
            float alpha = 1.f - __expf(-dens*(d1 - d0));
            scanA[wl][i] = 1.f - alpha + 1e-10f;
            sal[wl][i] = alpha;
            sdm[wl][i] = 0.5f*(d0 + d1);
        }
    }
    __syncwarp();

    {
        float (*src)[96] = scanA; float (*dst)[96] = scanB;
#pragma unroll
        for (int dstep = 1; dstep < 96; dstep <<= 1) {
#pragma unroll
            for (int sblk = 0; sblk < 3; sblk++) {
                int s = lane + sblk*32;
                float v = src[wl][s];
                if (s >= dstep) v *= src[wl][s - dstep];
                dst[wl][s] = v;
            }
            __syncwarp();
            float (*tmp)[96] = src; src = dst; dst = tmp;
        }
#pragma unroll
        for (int sblk = 0; sblk < 3; sblk++) {
            int i = lane + sblk*32;
            swt[wl][i] = (i >= 1) ? sal[wl][i] * src[wl][i-1] : 0.f;
        }
        if (lane == 0) swt[wl][96] = 0.f;
        __syncwarp();

        float wtp = 0.f, daccp = 0.f;
#pragma unroll
        for (int sblk = 0; sblk < 3; sblk++) {
            int i = lane + sblk*32;
            float w = swt[wl][i];
            wtp += w;
            daccp += w * sdm[wl][i];
            sal[wl][ord[wl][i]] = 0.5f*(swt[wl][i] + swt[wl][i+1]);
        }
        __syncwarp();
#pragma unroll
        for (int o = 16; o > 0; o >>= 1) {
            wtp   += __shfl_xor_sync(0xFFFFFFFFu, wtp, o);
            daccp += __shfl_xor_sync(0xFFFFFFFFu, daccp, o);
        }

        float acc = 0.f;
        const __half* pc = g_rgb_c + (size_t)ray*SC*32 + lane;
        const __half* pf = g_rgb_f + (size_t)ray*SFN*32 + lane;
#pragma unroll 8
        for (int k = 0; k < 48; k++) acc += sal[wl][k] * __half2float(pc[(size_t)k*32]);
#pragma unroll 8
        for (int k = 0; k < 48; k++) acc += sal[wl][48+k] * __half2float(pf[(size_t)k*32]);

        out[(size_t)ray*32 + lane] = acc*2.f - 1.f;
        if (lane == 0) {
            float depth = daccp / wtp;
            if (!isfinite(depth)) depth = ds[wl][ord[wl][95]];
            out[(size_t)NRAY*32 + ray] = depth;
            out[(size_t)NRAY*33 + ray] = wtp;
            out[(size_t)NRAY*34 + ray] = src[wl][95];
        }
    }
}

extern "C" void kernel_launch(void* const* d_in, const int* in_sizes, int n_in,
                              void* d_out, int out_size) {
    const float* planes = (const float*)d_in[0];
    const float* ro     = (const float*)d_in[1];
    const float* rd     = (const float*)d_in[2];
    const float* w1     = (const float*)d_in[3];
    const float* b1     = (const float*)d_in[4];
    const float* w2     = (const float*)d_in[5];
    const float* b2     = (const float*)d_in[6];
    const float* nstrat = (const float*)d_in[7];
    const float* nimp   = (const float*)d_in[8];
    float* out = (float*)d_out;

    k_trans_prep<<<dim3(RES*RES/128 + 1, 1, BB*3), dim3(32, 32)>>>(planes, w1, w2);
    k_eval_m<<<NSAMP/128, 128>>>(ro, rd, b1, b2, nstrat, /*fine=*/0);
    k_importance<<<(NRAY*32)/128, 128>>>(nimp);
    k_eval_m<<<NSAMP/128, 128>>>(ro, rd, b1, b2, nstrat, /*fine=*/1);
    k_final<<<(NRAY*32)/256, 256>>>(out);
}

// round 17
// speedup vs baseline: 1.2182x; 1.0386x over previous
#include <cuda_runtime.h>
#include <cuda_bf16.h>
#include <cuda_fp16.h>
#include <math.h>
#include <stdint.h>

// Problem constants
#define BB   2
#define RR   4096
#define SC   48
#define SFN  48
#define CF   32
#define RES  256
#define HID  64
#define ODIM 33
#define NRAY  (BB*RR)    // 8192
#define NSAMP (NRAY*SC)  // 393216

#define DELTA_F ((2.0f - 0.1f) / (float)(SC - 1))

typedef unsigned long long ull;

__device__ __forceinline__ float softplus_fast(float x) {
    float l = __logf(1.f + __expf(-fabsf(x)));
    return (x > 0.f) ? (x + l) : l;
}

__device__ __forceinline__ uint32_t smem_u32(const void* p) {
    uint32_t a;
    asm("{ .reg .u64 t; cvta.to.shared.u64 t, %1; cvt.u32.u64 %0, t; }" : "=r"(a) : "l"(p));
    return a;
}

// ---- mma / ldmatrix wrappers (base PTX) ----
__device__ __forceinline__ void ldsm_x4(uint32_t& r0, uint32_t& r1, uint32_t& r2, uint32_t& r3, uint32_t addr) {
    asm volatile("ldmatrix.sync.aligned.m8n8.x4.shared.b16 {%0,%1,%2,%3}, [%4];"
        : "=r"(r0), "=r"(r1), "=r"(r2), "=r"(r3) : "r"(addr));
}
__device__ __forceinline__ void mma16816h(float& d0, float& d1, float& d2, float& d3,
                                           uint32_t a0, uint32_t a1, uint32_t a2, uint32_t a3,
                                           uint32_t b0, uint32_t b1) {
    asm volatile("mma.sync.aligned.m16n8k16.row.col.f32.f16.f16.f32 "
        "{%0,%1,%2,%3}, {%4,%5,%6,%7}, {%8,%9}, {%0,%1,%2,%3};"
        : "+f"(d0), "+f"(d1), "+f"(d2), "+f"(d3)
        : "r"(a0), "r"(a1), "r"(a2), "r"(a3), "r"(b0), "r"(b1));
}

__device__ __forceinline__ uint32_t packhf(float lo, float hi) {
    __half2 h2; h2.x = __float2half_rn(lo); h2.y = __float2half_rn(hi);
    return *(uint32_t*)&h2;
}
__device__ __forceinline__ uint32_t hfma2u(uint32_t a, uint32_t b, uint32_t c) {
    __half2 r = __hfma2(*(__half2*)&a, *(__half2*)&b, *(__half2*)&c);
    return *(uint32_t*)&r;
}
__device__ __forceinline__ uint32_t hadd2u(uint32_t a, uint32_t b) {
    __half2 r = __hadd2(*(__half2*)&a, *(__half2*)&b);
    return *(uint32_t*)&r;
}

// -------- device scratch --------
__device__ __half g_planes_h[(size_t)BB*3*RES*RES*CF]; // [b,p,y,x,c] fp16, 25MB
__device__ float g_depths_c[NSAMP];
__device__ float g_depths_f[NSAMP];
__device__ float g_sigma_c[NSAMP];
__device__ float g_sigma_f[NSAMP];
__device__ __half g_rgb_c[(size_t)NSAMP*32];           // fp16 rgb, 24MB
__device__ __half g_rgb_f[(size_t)NSAMP*32];
__device__ uint32_t g_Bt1[64*32];    // 8KB
__device__ uint32_t g_Bt2[40*32];    // 5KB

// -------- merged: transpose planes to fp16 (4 m/thread) + weight prep --------
__global__ void k_trans_prep(const float* __restrict__ in,
                             const float* __restrict__ w1, const float* __restrict__ w2) {
    if (blockIdx.x == RES*RES/128) {
        if (blockIdx.z != 0) return;
        int t = threadIdx.y*32 + threadIdx.x;
        for (int i = t; i < 64*32; i += 1024) g_Bt1[i] = 0;
        for (int i = t; i < 40*32; i += 1024) g_Bt2[i] = 0;
        __syncthreads();
        for (int e = t; e < 64*32; e += 1024) {
            int n = e >> 5, k = e & 31;
            float v = w1[k*HID + n] * (1.f/3.f);
            uint32_t pos = (uint32_t)n*128u + ((((uint32_t)k >> 3) ^ (n & 7)) << 4) + (k & 7)*2u;
            *(__half*)((char*)g_Bt1 + pos) = __float2half_rn(v);
        }
        for (int e = t; e < 33*64; e += 1024) {
            int n = e >> 6, k = e & 63;
            int out = (n < 32) ? (n + 1) : 0;
            float v = w2[k*ODIM + out];
            uint32_t pos = (uint32_t)n*128u + ((((uint32_t)k >> 3) ^ (n & 7)) << 4) + (k & 7)*2u;
            *(__half*)((char*)g_Bt2 + pos) = __float2half_rn(v);
        }
        return;
    }
    __shared__ float tile[32][129];
    int bp = blockIdx.z;
    int m0 = blockIdx.x * 128;
    int tx = threadIdx.x, ty = threadIdx.y;
    const float* src = in + ((size_t)bp*CF + ty)*(RES*RES) + m0;
#pragma unroll
    for (int q = 0; q < 4; q++)
        tile[ty][tx + 32*q] = src[tx + 32*q];
    __syncthreads();
    __half* dst = g_planes_h + ((size_t)bp*(RES*RES) + m0)*CF;
#pragma unroll
    for (int q = 0; q < 4; q++) {
        int mm = ty*4 + q;
        dst[(size_t)mm*CF + tx] = __float2half_rn(tile[tx][mm]);
    }
}

// -------- fused eval: warp-independent phases, single early barrier --------
__global__ void __launch_bounds__(128, 5) k_eval_m(
    const float* __restrict__ ro, const float* __restrict__ rd,
    const float* __restrict__ b1, const float* __restrict__ b2,
    const float* __restrict__ nstrat, int fine)
{
    __shared__ __align__(16) char sA[128*128];
    __shared__ __align__(16) char sB1[64*128];
    __shared__ __align__(16) char sB2[40*128];
    __shared__ uint32_t sOff[6][128];
    __shared__ uint32_t sWgt[6][128];
    __shared__ float sb1[HID];
    __shared__ float sb2p[40];

    int tid = threadIdx.x;
    {
        uint4* d1 = (uint4*)sB1; const uint4* s1 = (const uint4*)g_Bt1;
        for (int i = tid; i < 512; i += 128) d1[i] = s1[i];
        uint4* d2 = (uint4*)sB2; const uint4* s2 = (const uint4*)g_Bt2;
        for (int i = tid; i < 320; i += 128) d2[i] = s2[i];
    }
    if (tid < HID) sb1[tid] = b1[tid];
    if (tid < 40)  sb2p[tid] = (tid < 32) ? b2[tid + 1] : ((tid == 32) ? b2[0] : 0.f);
    __syncthreads();

    int idx = blockIdx.x * 128 + tid;
    float*  sigma_out = fine ? g_sigma_f : g_sigma_c;
    __half* rgb_out   = fine ? g_rgb_f   : g_rgb_c;

    // ---- phase 1: per-sample offsets + corner weights ----
    {
        int ray = idx / SC;
        float t;
        if (fine) {
            t = g_depths_f[idx];
        } else {
            int s = idx % SC;
            t = 0.1f + (float)s * DELTA_F + nstrat[idx] * DELTA_F;
            g_depths_c[idx] = t;
        }
        int bb = (idx >= NSAMP/2) ? 1 : 0;
        float cc[3];
        cc[0] = (ro[ray*3+0] + t*rd[ray*3+0]) * 0.5f;
        cc[1] = (ro[ray*3+1] + t*rd[ray*3+1]) * 0.5f;
        cc[2] = (ro[ray*3+2] + t*rd[ray*3+2]) * 0.5f;
#pragma unroll
        for (int p = 0; p < 3; p++) {
            float x = ((cc[p] + 1.f)*(float)RES - 1.f)*0.5f;
            float y = ((cc[(p+1)%3] + 1.f)*(float)RES - 1.f)*0.5f;
            float x0f = floorf(x), y0f = floorf(y);
            float wx1 = x - x0f, wy1 = y - y0f;
            int x0 = (int)x0f, y0 = (int)y0f;
            int xs = min(max(x0, 0), RES-2);
            float wxc0 = (xs == x0) ? (1.f - wx1) : ((xs == x0+1) ? wx1 : 0.f);
            float wxc1 = (xs+1 == x0) ? (1.f - wx1) : ((xs+1 == x0+1) ? wx1 : 0.f);
            uint32_t pb = (uint32_t)(bb*3 + p) * (RES*RES*CF*2u);
#pragma unroll
            for (int cy = 0; cy < 2; cy++) {
                int yy = y0 + cy;
                float wyv = cy ? wy1 : (1.f - wy1);
                if (yy < 0 || yy >= RES) wyv = 0.f;
                int yyc = min(max(yy, 0), RES-1);
                sOff[p*2+cy][tid] = pb + (uint32_t)(yyc*RES + xs) * (CF*2u);
                sWgt[p*2+cy][tid] = packhf(wxc0*wyv, wxc1*wyv);
            }
        }
    }
    __syncwarp();

    int wid = tid >> 5, l = tid & 31;

    // ---- phase 2: cooperative gather (warp-local) ----
    {
        int bcorner = (l >> 2) & 1;
        int cb = l & 3;
        uint32_t lane_byte = (uint32_t)(l & 7) * 16u;
        const char* pbase = (const char*)g_planes_h;
#pragma unroll 1
        for (int g = 0; g < 8; g++) {
            int s_loc = wid*32 + g*4 + (l >> 3);

            uint32_t wu[6];
            const uint4* addr[6];
#pragma unroll
            for (int j = 0; j < 6; j++) {
                uint32_t off = sOff[j][s_loc];
                uint32_t w2 = sWgt[j][s_loc];
                uint32_t h = bcorner ? (w2 >> 16) : (w2 & 0xFFFFu);
                wu[j] = h | (h << 16);
                addr[j] = (const uint4*)(pbase + off + lane_byte);
            }
            uint4 v[6];
#pragma unroll
            for (int j = 0; j < 6; j++) v[j] = *addr[j];

            uint32_t acc[4] = {0u, 0u, 0u, 0u};
#pragma unroll
            for (int j = 0; j < 6; j++) {
                const uint32_t* hp = (const uint32_t*)&v[j];
#pragma unroll
                for (int h = 0; h < 4; h++)
                    acc[h] = hfma2u(wu[j], hp[h], acc[h]);
            }
#pragma unroll
            for (int h = 0; h < 4; h++) {
                uint32_t other = __shfl_xor_sync(0xFFFFFFFFu, acc[h], 4);
                acc[h] = hadd2u(acc[h], other);
            }
            if (!(l & 4)) {
                uint32_t rb = (uint32_t)s_loc * 128u;
                uint32_t sw = (uint32_t)(s_loc & 7);
                *(uint4*)(sA + rb + ((((uint32_t)cb) ^ sw) << 4)) = make_uint4(acc[0], acc[1], acc[2], acc[3]);
            }
        }
    }
    __syncwarp();

    uint32_t aBase  = smem_u32(sA);
    uint32_t b1Base = smem_u32(sB1);
    uint32_t b2Base = smem_u32(sB2);

    int lq = l >> 2;
    int lr2 = (l & 3) * 2;

#pragma unroll
    for (int m = 0; m < 2; m++) {
        int R = wid*32 + m*16;

        uint32_t af[2][4];
        {
            int arow = R + (l & 7) + 8*((l >> 3) & 1);
            uint32_t aseg = (uint32_t)(l >> 4);
            uint32_t rb = (uint32_t)arow * 128u;
            uint32_t sw = (uint32_t)(arow & 7);
#pragma unroll
            for (int kt = 0; kt < 2; kt++) {
                uint32_t addr = aBase + rb + ((((uint32_t)kt*2u + aseg) ^ sw) << 4);
                ldsm_x4(af[kt][0], af[kt][1], af[kt][2], af[kt][3], addr);
            }
        }

        // layer 1: D = a * W (K=32)
        uint32_t a2f[4][4];
        {
            int brow = (l & 7);
            uint32_t bchunk = (uint32_t)(l >> 3);
#pragma unroll
            for (int nt = 0; nt < 8; nt++) {
                int bn = nt*8 + brow;
                uint32_t brb = (uint32_t)bn * 128u;
                uint32_t bsw = (uint32_t)(bn & 7);
                uint32_t hA0, hA1, hB0, hB1;
                ldsm_x4(hA0, hA1, hB0, hB1, b1Base + brb + ((bchunk ^ bsw) << 4));
                float d0 = 0.f, d1 = 0.f, d2 = 0.f, d3 = 0.f;
                mma16816h(d0,d1,d2,d3, af[0][0],af[0][1],af[0][2],af[0][3], hA0,hA1);
                mma16816h(d0,d1,d2,d3, af[1][0],af[1][1],af[1][2],af[1][3], hB0,hB1);

                int col0 = nt*8 + lr2;
                float s0 = softplus_fast(d0 + sb1[col0]);
                float s1 = softplus_fast(d1 + sb1[col0+1]);
                float s2 = softplus_fast(d2 + sb1[col0]);
                float s3 = softplus_fast(d3 + sb1[col0+1]);
                int kk = nt >> 1, half = nt & 1;
                a2f[kk][2*half+0] = packhf(s0, s1);
                a2f[kk][2*half+1] = packhf(s2, s3);
            }
        }

        // layer 2: D = h * W (K=64) ; N=40 permuted
        {
            int brow = (l & 7);
            uint32_t bchunk = (uint32_t)(l >> 3);
            int r0 = blockIdx.x*128 + R + lq;
            int r1 = r0 + 8;
#pragma unroll
            for (int nt2 = 0; nt2 < 5; nt2++) {
                int bn = nt2*8 + brow;
                uint32_t brb = (uint32_t)bn * 128u;
                uint32_t bsw = (uint32_t)(bn & 7);
                uint32_t e0r[4], e1r[4];
                ldsm_x4(e0r[0], e0r[1], e0r[2], e0r[3], b2Base + brb + (((bchunk      ) ^ bsw) << 4));
                ldsm_x4(e1r[0], e1r[1], e1r[2], e1r[3], b2Base + brb + (((4u + bchunk) ^ bsw) << 4));

                float d0 = 0.f, d1 = 0.f, d2 = 0.f, d3 = 0.f;
                mma16816h(d0,d1,d2,d3, a2f[0][0],a2f[0][1],a2f[0][2],a2f[0][3], e0r[0],e0r[1]);
                mma16816h(d0,d1,d2,d3, a2f[1][0],a2f[1][1],a2f[1][2],a2f[1][3], e0r[2],e0r[3]);
                mma16816h(d0,d1,d2,d3, a2f[2][0],a2f[2][1],a2f[2][2],a2f[2][3], e1r[0],e1r[1]);
                mma16816h(d0,d1,d2,d3, a2f[3][0],a2f[3][1],a2f[3][2],a2f[3][3], e1r[2],e1r[3]);

                int col0 = nt2*8 + lr2;
                if (nt2 < 4) {
                    float v0 = __fdividef(1.002f, 1.f + __expf(-(d0 + sb2p[col0])))   - 0.001f;
                    float v1 = __fdividef(1.002f, 1.f + __expf(-(d1 + sb2p[col0+1]))) - 0.001f;
                    float v2 = __fdividef(1.002f, 1.f + __expf(-(d2 + sb2p[col0])))   - 0.001f;
                    float v3 = __fdividef(1.002f, 1.f + __expf(-(d3 + sb2p[col0+1]))) - 0.001f;
                    *(uint32_t*)&rgb_out[(size_t)r0*32 + col0] = packhf(v0, v1);
                    *(uint32_t*)&rgb_out[(size_t)r1*32 + col0] = packhf(v2, v3);
                } else if (lr2 == 0) {
                    sigma_out[r0] = d0 + sb2p[32];
                    sigma_out[r1] = d2 + sb2p[32];
                }
            }
        }
    }
}

// -------- warp-per-ray importance: fully warp-parallel scans --------
__global__ void __launch_bounds__(128, 8) k_importance(const float* __restrict__ nimp) {
    int gw   = (blockIdx.x * 128 + threadIdx.x) >> 5;
    int lane = threadIdx.x & 31;
    int wl   = threadIdx.x >> 5;
    __shared__ float sh_d[4][48], sh_s[4][48];
    __shared__ float sh_a[4][48];      // alpha, then pw
    __shared__ float sh_w[4][48];      // scan buf A / w
    __shared__ float sh_x[4][48];      // scan buf B
    __shared__ float sh_cdf[4][46];
    __shared__ float sh_bins[4][48];
    if (gw >= NRAY) return;

    const float* dp = g_depths_c + (size_t)gw*SC;
    const float* sp = g_sigma_c  + (size_t)gw*SC;
    for (int i = lane; i < 48; i += 32) { sh_d[wl][i] = dp[i]; sh_s[wl][i] = sp[i]; }
    __syncwarp();

    // alpha/bins/q  (q in sh_w, slot 47 = 1)
    for (int i = lane; i < 48; i += 32) {
        if (i < 47) {
            float d0 = sh_d[wl][i], d1 = sh_d[wl][i+1];
            float dens = softplus_fast(0.5f*(sh_s[wl][i] + sh_s[wl][i+1]) - 1.f);
            float a = 1.f - __expf(-dens*(d1 - d0));
            sh_a[wl][i]    = a;
            sh_w[wl][i]    = 1.f - a + 1e-10f;
            sh_bins[wl][i] = 0.5f*(d0 + d1);
        } else {
            sh_w[wl][i] = 1.f;
        }
    }
    __syncwarp();

    // prefix product over 48 slots (Hillis-Steele, 6 steps)
    {
        float (*src)[48] = sh_w; float (*dst)[48] = sh_x;
#pragma unroll
        for (int st = 1; st < 48; st <<= 1) {
#pragma unroll
            for (int sb = 0; sb < 2; sb++) {
                int s = lane + sb*32;
                if (s < 48) {
                    float v = src[wl][s];
                    if (s >= st) v *= src[wl][s - st];
                    dst[wl][s] = v;
                }
            }
            __syncwarp();
            float (*tmp)[48] = src; src = dst; dst = tmp;
        }
        // P in src. w_i = a_i * P_{i-1}; store to sh_s (free)
        for (int i = lane; i < 47; i += 32)
            sh_s[wl][i] = sh_a[wl][i] * ((i >= 1) ? src[wl][i-1] : 1.f);
    }
    __syncwarp();

    // pw[j] = 0.5*(max(w[j],w[j+1]) + max(w[j+1],w[j+2])) + 0.01 + 1e-5 ; into sh_w slots, pad 0
    for (int j = lane; j < 48; j += 32) {
        if (j < 45) {
            float m1 = fmaxf(sh_s[wl][j],   sh_s[wl][j+1]);
            float m2 = fmaxf(sh_s[wl][j+1], sh_s[wl][j+2]);
            sh_w[wl][j] = 0.5f*(m1 + m2) + 0.01f + 1e-5f;
        } else {
            sh_w[wl][j] = 0.f;
        }
    }
    __syncwarp();

    // prefix sum over 48 slots
    {
        float (*src)[48] = sh_w; float (*dst)[48] = sh_x;
#pragma unroll
        for (int st = 1; st < 48; st <<= 1) {
#pragma unroll
            for (int sb = 0; sb < 2; sb++) {
                int s = lane + sb*32;
                if (s < 48) {
                    float v = src[wl][s];
                    if (s >= st) v += src[wl][s - st];
                    dst[wl][s] = v;
                }
            }
            __syncwarp();
            float (*tmp)[48] = src; src = dst; dst = tmp;
        }
        float inv = __fdividef(1.f, src[wl][44]);
        for (int j = lane; j < 46; j += 32)
            sh_cdf[wl][j] = (j == 0) ? 0.f : src[wl][j-1] * inv;
    }
    __syncwarp();

    const float* up = nimp + (size_t)gw*SFN;
    float* outp = g_depths_f + (size_t)gw*SFN;
    for (int j = lane; j < SFN; j += 32) {
        float u = up[j];
        int ind = 0;
#pragma unroll
        for (int t2 = 0; t2 < 46; t2++) ind += (sh_cdf[wl][t2] <= u) ? 1 : 0;
        int below = ind - 1; if (below < 0) below = 0;
        int above = ind;     if (above > 45) above = 45;
        float cb = sh_cdf[wl][below], ca = sh_cdf[wl][above];
        float bb = sh_bins[wl][below], ba = sh_bins[wl][above];
        float den = ca - cb; if (den < 1e-5f) den = 1.f;
        outp[j] = bb + (u - cb)/den * (ba - bb);
    }
}

// -------- merge, half-cost rank sort (coarse pre-sorted), scan march --------
__global__ void __launch_bounds__(256) k_final(float* __restrict__ out) {
    int warp = (blockIdx.x * blockDim.x + threadIdx.x) >> 5;
    int lane = threadIdx.x & 31;
    int wl   = threadIdx.x >> 5;
    __shared__ float ds[8][96];
    __shared__ float ss[8][96];
    __shared__ int   ord[8][96];
    __shared__ float scanA[8][96];
    __shared__ float scanB[8][96];
    __shared__ float sal[8][96];
    __shared__ float sdm[8][96];
    __shared__ float swt[8][97];
    if (warp >= NRAY) return;
    int ray = warp;

    for (int k = lane; k < 96; k += 32) {
        float dv, sv;
        if (k < SC) { dv = g_depths_c[(size_t)ray*SC + k]; sv = g_sigma_c[(size_t)ray*SC + k]; }
        else        { dv = g_depths_f[(size_t)ray*SFN + k - SC]; sv = g_sigma_f[(size_t)ray*SFN + k - SC]; }
        ds[wl][k] = dv; ss[wl][k] = sv;
    }
    __syncwarp();

    // rank sort exploiting strictly-increasing coarse depths:
    //  coarse k: rank = k + #{fine < d_k}
    //  fine   k: rank = #{coarse <= d_k} + #{fine stable-< d_k}
    for (int k = lane; k < 96; k += 32) {
        float di = ds[wl][k];
        int r;
        if (k < SC) {
            r = k;
            for (int j = SC; j < 96; j++) r += (ds[wl][j] < di) ? 1 : 0;
        } else {
            r = 0;
            for (int j = 0; j < SC; j++) r += (ds[wl][j] <= di) ? 1 : 0;
            for (int j = SC; j < 96; j++) {
                float dj = ds[wl][j];
                r += ((dj < di) || (dj == di && j < k)) ? 1 : 0;
            }
        }
        ord[wl][r] = k;
    }
    __syncwarp();

#pragma unroll
    for (int sblk = 0; sblk < 3; sblk++) {
        int i = lane + sblk*32;
        if (i == 0) {
            scanA[wl][0] = 1.f;
            sal[wl][0] = 0.f;
            sdm[wl][0] = 0.f;
        } else {
            int ip = ord[wl][i-1], ic = ord[wl][i];
            float d0 = ds[wl][ip], d1 = ds[wl][ic];
            float s0 = ss[wl][ip], s1 = ss[wl][ic];
            float dens  = softplus_fast(0.5f*(s0 + s1) - 1.f);
            float alpha = 1.f - __expf(-dens*(d1 - d0));
            scanA[wl][i] = 1.f - alpha + 1e-10f;
            sal[wl][i] = alpha;
            sdm[wl][i] = 0.5f*(d0 + d1);
        }
    }
    __syncwarp();

    {
        float (*src)[96] = scanA; float (*dst)[96] = scanB;
#pragma unroll
        for (int dstep = 1; dstep < 96; dstep <<= 1) {
#pragma unroll
            for (int sblk = 0; sblk < 3; sblk++) {
                int s = lane + sblk*32;
                float v = src[wl][s];
                if (s >= dstep) v *= src[wl][s - dstep];
                dst[wl][s] = v;
            }
            __syncwarp();
            float (*tmp)[96] = src; src = dst; dst = tmp;
        }
#pragma unroll
        for (int sblk = 0; sblk < 3; sblk++) {
            int i = lane + sblk*32;
            swt[wl][i] = (i >= 1) ? sal[wl][i] * src[wl][i-1] : 0.f;
        }
        if (lane == 0) swt[wl][96] = 0.f;
        __syncwarp();

        float wtp = 0.f, daccp = 0.f;
#pragma unroll
        for (int sblk = 0; sblk < 3; sblk++) {
            int i = lane + sblk*32;
            float w = swt[wl][i];
            wtp += w;
            daccp += w * sdm[wl][i];
            sal[wl][ord[wl][i]] = 0.5f*(swt[wl][i] + swt[wl][i+1]);
        }
        __syncwarp();
#pragma unroll
        for (int o = 16; o > 0; o >>= 1) {
            wtp   += __shfl_xor_sync(0xFFFFFFFFu, wtp, o);
            daccp += __shfl_xor_sync(0xFFFFFFFFu, daccp, o);
        }

        float acc = 0.f;
        const __half* pc = g_rgb_c + (size_t)ray*SC*32 + lane;
        const __half* pf = g_rgb_f + (size_t)ray*SFN*32 + lane;
#pragma unroll 8
        for (int k = 0; k < 48; k++) acc += sal[wl][k] * __half2float(pc[(size_t)k*32]);
#pragma unroll 8
        for (int k = 0; k < 48; k++) acc += sal[wl][48+k] * __half2float(pf[(size_t)k*32]);

        out[(size_t)ray*32 + lane] = acc*2.f - 1.f;
        if (lane == 0) {
            float depth = daccp / wtp;
            if (!isfinite(depth)) depth = ds[wl][ord[wl][95]];
            out[(size_t)NRAY*32 + ray] = depth;
            out[(size_t)NRAY*33 + ray] = wtp;
            out[(size_t)NRAY*34 + ray] = src[wl][95];
        }
    }
}

extern "C" void kernel_launch(void* const* d_in, const int* in_sizes, int n_in,
                              void* d_out, int out_size) {
    const float* planes = (const float*)d_in[0];
    const float* ro     = (const float*)d_in[1];
    const float* rd     = (const float*)d_in[2];
    const float* w1     = (const float*)d_in[3];
    const float* b1     = (const float*)d_in[4];
    const float* w2     = (const float*)d_in[5];
    const float* b2     = (const float*)d_in[6];
    const float* nstrat = (const float*)d_in[7];
    const float* nimp   = (const float*)d_in[8];
    float* out = (float*)d_out;

    k_trans_prep<<<dim3(RES*RES/128 + 1, 1, BB*3), dim3(32, 32)>>>(planes, w1, w2);
    k_eval_m<<<NSAMP/128, 128>>>(ro, rd, b1, b2, nstrat, /*fine=*/0);
    k_importance<<<(NRAY*32)/128, 128>>>(nimp);
    k_eval_m<<<NSAMP/128, 128>>>(ro, rd, b1, b2, nstrat, /*fine=*/1);
    k_final<<<(NRAY*32)/256, 256>>>(out);
}